// round 1
// baseline (speedup 1.0000x reference)
#include <cuda_runtime.h>

#define NN 50000
#define NE 800000

// ---------------- scratch (device globals: allocation-free) ----------------
__device__ float g_node[NN * 32];
__device__ float g_P[NN * 32];
__device__ float g_Q[NN * 32];
__device__ float g_pvc[NN * 32];
__device__ float g_a[NN * 32];
__device__ int   g_cnt[NN];
__device__ int   g_off[NN + 1];
__device__ int   g_cur[NN];
__device__ int   g_csr[2 * NE];

// ---------------- small helpers ----------------
__global__ void zero_cnt_kernel(int n) {
    int i = blockIdx.x * blockDim.x + threadIdx.x;
    if (i < n) g_cnt[i] = 0;
}

// node0 = classes @ W_in.T + b_in ; pvc = pos @ W1c.T  (once per launch)
__global__ void embed_pvc_kernel(const float* __restrict__ classes,
                                 const float* __restrict__ pos,
                                 const float* __restrict__ Win,
                                 const float* __restrict__ bin,
                                 const float* __restrict__ W1,
                                 int n_nodes) {
    int warp = (blockIdx.x * blockDim.x + threadIdx.x) >> 5;
    int j = threadIdx.x & 31;
    if (warp >= n_nodes) return;
    int u = warp;

    float w[16];
#pragma unroll
    for (int k = 0; k < 16; k++) w[k] = Win[j * 16 + k];
    float c = (j < 16) ? classes[u * 16 + j] : 0.f;
    float acc = bin[j];
#pragma unroll
    for (int k = 0; k < 16; k++)
        acc = fmaf(w[k], __shfl_sync(0xffffffffu, c, k), acc);
    g_node[u * 32 + j] = acc;

    float p0 = pos[u * 3 + 0], p1 = pos[u * 3 + 1], p2 = pos[u * 3 + 2];
    float pv = p0 * W1[j * 67 + 64] + p1 * W1[j * 67 + 65] + p2 * W1[j * 67 + 66];
    g_pvc[u * 32 + j] = pv;
}

// Directed-edge identity: esym[0][i] == edges_flat[i] for all i in [0, 2E)
__global__ void count_kernel(const int* __restrict__ e, int n2e) {
    int i = blockIdx.x * blockDim.x + threadIdx.x;
    if (i < n2e) atomicAdd(&g_cnt[e[i]], 1);
}

// single-block Hillis-Steele scan over g_cnt -> exclusive offsets g_off
__global__ void scan_kernel(int n) {
    __shared__ int sh[1024];
    __shared__ int s_carry;
    int tid = threadIdx.x;
    if (tid == 0) { g_off[0] = 0; s_carry = 0; }
    __syncthreads();
    for (int base = 0; base < n; base += 1024) {
        int x = (base + tid < n) ? g_cnt[base + tid] : 0;
        sh[tid] = x;
        __syncthreads();
        for (int o = 1; o < 1024; o <<= 1) {
            int v = (tid >= o) ? sh[tid - o] : 0;
            __syncthreads();
            sh[tid] += v;
            __syncthreads();
        }
        int incl = sh[tid] + s_carry;
        if (base + tid < n) g_off[base + tid + 1] = incl;
        __syncthreads();
        if (tid == 1023) s_carry = incl;
        __syncthreads();
    }
}

__global__ void init_cur_kernel(int n) {
    int i = blockIdx.x * blockDim.x + threadIdx.x;
    if (i < n) g_cur[i] = g_off[i];
}

__global__ void scatter_kernel(const int* __restrict__ e, int nE) {
    int i = blockIdx.x * blockDim.x + threadIdx.x;
    if (i >= 2 * nE) return;
    int src = e[i];
    int dst = (i < nE) ? e[i + nE] : e[i - nE];
    int slot = atomicAdd(&g_cur[src], 1);
    g_csr[slot] = dst;
}

// per-iteration: P = node@W1a.T + b1 - pvc ; Q = node@W1b.T + pvc
__global__ void pq_kernel(const float* __restrict__ W1,
                          const float* __restrict__ b1, int n_nodes) {
    int warp = (blockIdx.x * blockDim.x + threadIdx.x) >> 5;
    int j = threadIdx.x & 31;
    if (warp >= n_nodes) return;
    int u = warp;
    float wa[32], wb[32];
#pragma unroll
    for (int k = 0; k < 32; k++) {
        wa[k] = W1[j * 67 + k];
        wb[k] = W1[j * 67 + 32 + k];
    }
    float nd = g_node[u * 32 + j];
    float p = 0.f, q = 0.f;
#pragma unroll
    for (int k = 0; k < 32; k++) {
        float v = __shfl_sync(0xffffffffu, nd, k);
        p = fmaf(wa[k], v, p);
        q = fmaf(wb[k], v, q);
    }
    float pv = g_pvc[u * 32 + j];
    g_P[u * 32 + j] = p + b1[j] - pv;
    g_Q[u * 32 + j] = q + pv;
}

// the heavy kernel: warp per node, fused edge-MLP (layers 2,3) + register
// segment-sum over the node's CSR out-edges.
__global__ void __launch_bounds__(256) edge_kernel(
        const float* __restrict__ W2, const float* __restrict__ b2,
        const float* __restrict__ W3, const float* __restrict__ b3,
        int n_nodes) {
    int warp = (blockIdx.x * blockDim.x + threadIdx.x) >> 5;
    int j = threadIdx.x & 31;
    if (warp >= n_nodes) return;
    int u = warp;

    float w2[32], w3[32];
#pragma unroll
    for (int k = 0; k < 32; k++) {
        w2[k] = W2[j * 32 + k];
        w3[k] = W3[j * 32 + k];
    }
    float bb2 = b2[j], bb3 = b3[j];
    float pj = g_P[u * 32 + j];
    float acc = 0.f;

    int s = g_off[u], eEnd = g_off[u + 1];
    for (int base = s; base < eEnd; base += 32) {
        int idx = base + j;
        int v = (idx < eEnd) ? g_csr[idx] : 0;
        int cnt = min(32, eEnd - base);
        for (int t = 0; t < cnt; t++) {
            int vv = __shfl_sync(0xffffffffu, v, t);
            // layer 1 collapses to add+relu thanks to P/Q/pvc factorization
            float h1 = fmaxf(pj + g_Q[vv * 32 + j], 0.f);
            float h2 = bb2;
#pragma unroll
            for (int k = 0; k < 32; k++)
                h2 = fmaf(w2[k], __shfl_sync(0xffffffffu, h1, k), h2);
            h2 = fmaxf(h2, 0.f);
            float m = bb3;
#pragma unroll
            for (int k = 0; k < 32; k++)
                m = fmaf(w3[k], __shfl_sync(0xffffffffu, h2, k), m);
            acc += m;
        }
    }
    g_a[u * 32 + j] = acc;
}

// GRU cell on nodes (torch gate order r,z,n). Weights transposed+packed in smem.
__global__ void gru_kernel(const float* __restrict__ Wih,
                           const float* __restrict__ Whh,
                           const float* __restrict__ bih,
                           const float* __restrict__ bhh,
                           float* __restrict__ out, int n_nodes) {
    __shared__ float4 sWi[32][32];
    __shared__ float4 sWh[32][32];
    int tid = threadIdx.x;
    for (int idx = tid; idx < 1024; idx += blockDim.x) {
        int k = idx >> 5, j = idx & 31;
        sWi[k][j] = make_float4(Wih[j * 32 + k], Wih[(j + 32) * 32 + k],
                                Wih[(j + 64) * 32 + k], 0.f);
        sWh[k][j] = make_float4(Whh[j * 32 + k], Whh[(j + 32) * 32 + k],
                                Whh[(j + 64) * 32 + k], 0.f);
    }
    __syncthreads();

    int j = tid & 31;
    int warp = tid >> 5;
    int wpb = blockDim.x >> 5;
    float br = bih[j], bz = bih[j + 32], bn = bih[j + 64];
    float cr = bhh[j], cz = bhh[j + 32], cn = bhh[j + 64];

    for (int u = blockIdx.x * wpb + warp; u < n_nodes; u += gridDim.x * wpb) {
        float x = g_a[u * 32 + j];
        float h = g_node[u * 32 + j];
        float gir = br, giz = bz, gin = bn, ghr = cr, ghz = cz, ghn = cn;
#pragma unroll
        for (int k = 0; k < 32; k++) {
            float xa = __shfl_sync(0xffffffffu, x, k);
            float hb = __shfl_sync(0xffffffffu, h, k);
            float4 wi = sWi[k][j];
            float4 wh = sWh[k][j];
            gir = fmaf(wi.x, xa, gir); giz = fmaf(wi.y, xa, giz); gin = fmaf(wi.z, xa, gin);
            ghr = fmaf(wh.x, hb, ghr); ghz = fmaf(wh.y, hb, ghz); ghn = fmaf(wh.z, hb, ghn);
        }
        float r = 1.f / (1.f + expf(-(gir + ghr)));
        float z = 1.f / (1.f + expf(-(giz + ghz)));
        float nval = tanhf(gin + r * ghn);
        float nh = (1.f - z) * nval + z * h;
        g_node[u * 32 + j] = nh;
        if (out) out[u * 32 + j] = nh;
    }
}

// ---------------- launch ----------------
extern "C" void kernel_launch(void* const* d_in, const int* in_sizes, int n_in,
                              void* d_out, int out_size) {
    const float* pos     = (const float*)d_in[0];
    const float* classes = (const float*)d_in[1];
    const int*   edges   = (const int*)d_in[2];
    // n_graphs may or may not be materialized as an input; detect by size.
    int wb = (in_sizes[3] == 1) ? 4 : 3;
    const float* Win = (const float*)d_in[wb + 0];
    const float* bin = (const float*)d_in[wb + 1];
    const float* W1  = (const float*)d_in[wb + 2];
    const float* b1  = (const float*)d_in[wb + 3];
    const float* W2  = (const float*)d_in[wb + 4];
    const float* b2  = (const float*)d_in[wb + 5];
    const float* W3  = (const float*)d_in[wb + 6];
    const float* b3  = (const float*)d_in[wb + 7];
    const float* Wih = (const float*)d_in[wb + 8];
    const float* Whh = (const float*)d_in[wb + 9];
    const float* bih = (const float*)d_in[wb + 10];
    const float* bhh = (const float*)d_in[wb + 11];

    int n_nodes = in_sizes[0] / 3;
    int n_edges = in_sizes[2] / 2;
    int n2e = 2 * n_edges;
    float* out = (float*)d_out;

    // once-per-launch prep
    zero_cnt_kernel<<<(n_nodes + 255) / 256, 256>>>(n_nodes);
    embed_pvc_kernel<<<(n_nodes + 7) / 8, 256>>>(classes, pos, Win, bin, W1, n_nodes);
    count_kernel<<<(n2e + 255) / 256, 256>>>(edges, n2e);
    scan_kernel<<<1, 1024>>>(n_nodes);
    init_cur_kernel<<<(n_nodes + 255) / 256, 256>>>(n_nodes);
    scatter_kernel<<<(n2e + 255) / 256, 256>>>(edges, n_edges);

    for (int it = 0; it < 6; ++it) {
        pq_kernel<<<(n_nodes + 7) / 8, 256>>>(W1, b1, n_nodes);
        edge_kernel<<<(n_nodes + 7) / 8, 256>>>(W2, b2, W3, b3, n_nodes);
        gru_kernel<<<512, 256>>>(Wih, Whh, bih, bhh,
                                 (it == 5) ? out : (float*)nullptr, n_nodes);
    }
}

// round 2
// speedup vs baseline: 1.3536x; 1.3536x over previous
#include <cuda_runtime.h>

#define NN 50000
#define NE 800000

// ---------------- scratch (device globals: allocation-free) ----------------
__device__ float g_node[NN * 32];
__device__ float g_P[NN * 32];
__device__ float g_Q[NN * 32];
__device__ float g_pvc[NN * 32];
__device__ float g_a[NN * 32];
__device__ int   g_cnt[NN];
__device__ int   g_off[NN + 1];
__device__ int   g_cur[NN];
__device__ int   g_csr[2 * NE];

// ---------------- small helpers ----------------
__global__ void zero_cnt_kernel(int n) {
    int i = blockIdx.x * blockDim.x + threadIdx.x;
    if (i < n) g_cnt[i] = 0;
}

// node0 = classes @ W_in.T + b_in ; pvc = pos @ W1c.T  (once per launch)
__global__ void embed_pvc_kernel(const float* __restrict__ classes,
                                 const float* __restrict__ pos,
                                 const float* __restrict__ Win,
                                 const float* __restrict__ bin,
                                 const float* __restrict__ W1,
                                 int n_nodes) {
    int warp = (blockIdx.x * blockDim.x + threadIdx.x) >> 5;
    int j = threadIdx.x & 31;
    if (warp >= n_nodes) return;
    int u = warp;

    float w[16];
#pragma unroll
    for (int k = 0; k < 16; k++) w[k] = Win[j * 16 + k];
    float c = (j < 16) ? classes[u * 16 + j] : 0.f;
    float acc = bin[j];
#pragma unroll
    for (int k = 0; k < 16; k++)
        acc = fmaf(w[k], __shfl_sync(0xffffffffu, c, k), acc);
    g_node[u * 32 + j] = acc;

    float p0 = pos[u * 3 + 0], p1 = pos[u * 3 + 1], p2 = pos[u * 3 + 2];
    float pv = p0 * W1[j * 67 + 64] + p1 * W1[j * 67 + 65] + p2 * W1[j * 67 + 66];
    g_pvc[u * 32 + j] = pv;
}

// Directed-edge identity: esym[0][i] == edges_flat[i] for all i in [0, 2E)
__global__ void count_kernel(const int* __restrict__ e, int n2e) {
    int i = blockIdx.x * blockDim.x + threadIdx.x;
    if (i < n2e) atomicAdd(&g_cnt[e[i]], 1);
}

// single-block scan: per-thread serial chunk sums + shfl block scan + serial write
__global__ void scan_kernel(int n) {
    const int T = 1024;
    int tid = threadIdx.x;
    int chunk = (n + T - 1) / T;
    int beg = tid * chunk;
    int end = min(beg + chunk, n);
    if (beg > n) beg = n;

    int s = 0;
    for (int i = beg; i < end; i++) s += g_cnt[i];

    __shared__ int warp_tot[32];
    int lane = tid & 31, wid = tid >> 5;
    int v = s;
#pragma unroll
    for (int o = 1; o < 32; o <<= 1) {
        int t = __shfl_up_sync(0xffffffffu, v, o);
        if (lane >= o) v += t;
    }
    if (lane == 31) warp_tot[wid] = v;
    __syncthreads();
    if (wid == 0) {
        int w = warp_tot[lane];
#pragma unroll
        for (int o = 1; o < 32; o <<= 1) {
            int t = __shfl_up_sync(0xffffffffu, w, o);
            if (lane >= o) w += t;
        }
        warp_tot[lane] = w;
    }
    __syncthreads();
    int excl = (v - s) + (wid > 0 ? warp_tot[wid - 1] : 0);

    int run = excl;
    for (int i = beg; i < end; i++) {
        g_off[i] = run;
        run += g_cnt[i];
    }
    if (end == n) g_off[n] = run;  // trailing threads all carry run == total
}

__global__ void init_cur_kernel(int n) {
    int i = blockIdx.x * blockDim.x + threadIdx.x;
    if (i < n) g_cur[i] = g_off[i];
}

__global__ void scatter_kernel(const int* __restrict__ e, int nE) {
    int i = blockIdx.x * blockDim.x + threadIdx.x;
    if (i >= 2 * nE) return;
    int src = e[i];
    int dst = (i < nE) ? e[i + nE] : e[i - nE];
    int slot = atomicAdd(&g_cur[src], 1);
    g_csr[slot] = dst;
}

// per-iteration: P = node@W1a.T + b1 - pvc ; Q = node@W1b.T + pvc
__global__ void pq_kernel(const float* __restrict__ W1,
                          const float* __restrict__ b1, int n_nodes) {
    int warp = (blockIdx.x * blockDim.x + threadIdx.x) >> 5;
    int j = threadIdx.x & 31;
    if (warp >= n_nodes) return;
    int u = warp;
    float wa[32], wb[32];
#pragma unroll
    for (int k = 0; k < 32; k++) {
        wa[k] = W1[j * 67 + k];
        wb[k] = W1[j * 67 + 32 + k];
    }
    float nd = g_node[u * 32 + j];
    float p = 0.f, q = 0.f;
#pragma unroll
    for (int k = 0; k < 32; k++) {
        float v = __shfl_sync(0xffffffffu, nd, k);
        p = fmaf(wa[k], v, p);
        q = fmaf(wb[k], v, q);
    }
    float pv = g_pvc[u * 32 + j];
    g_P[u * 32 + j] = p + b1[j] - pv;
    g_Q[u * 32 + j] = q + pv;
}

// Hot kernel: warp per node. For each 32-edge chunk:
//   pass1: stage h1 = relu(P[u]+Q[v]) tile [32 edges x 32 feat] into smem
//          (coalesced g_Q loads, conflict-free STS)
//   pass2: lane j computes h2[t][j] via LDS.128 broadcast reads + register
//          weights, accumulates relu(h2) into acc_j.
// Layer 3 commutes with the segment-sum (affine):
//   a[u] = acc @ W3.T + deg(u)*b3   -> per-node epilogue.
__global__ void __launch_bounds__(256) edge_kernel(
        const float* __restrict__ W2, const float* __restrict__ b2,
        const float* __restrict__ W3, const float* __restrict__ b3,
        int n_nodes) {
    __shared__ float A_s[8][32][32];   // 32KB: per-warp h1 tile
    int warp = (blockIdx.x * blockDim.x + threadIdx.x) >> 5;
    int wl = threadIdx.x >> 5;
    int j = threadIdx.x & 31;
    if (warp >= n_nodes) return;
    float (*A)[32] = A_s[wl];
    int u = warp;

    float w2[32];
#pragma unroll
    for (int k = 0; k < 32; k++) w2[k] = W2[j * 32 + k];
    float bb2 = b2[j];
    float pj = g_P[u * 32 + j];
    float acc = 0.f;

    int s = g_off[u], eEnd = g_off[u + 1];
    for (int base = s; base < eEnd; base += 32) {
        int cnt = min(32, eEnd - base);
        int v = (base + j < eEnd) ? g_csr[base + j] : 0;
        __syncwarp();  // protect smem tile against prior pass2 readers
        if (cnt == 32) {
#pragma unroll 8
            for (int t = 0; t < 32; t++) {
                int vv = __shfl_sync(0xffffffffu, v, t);
                A[t][j] = fmaxf(pj + g_Q[vv * 32 + j], 0.f);
            }
            __syncwarp();
#pragma unroll 2
            for (int t = 0; t < 32; t++) {
                const float4* row = (const float4*)A[t];
                float h0 = bb2, h1 = 0.f, h2 = 0.f, h3 = 0.f;
#pragma unroll
                for (int c = 0; c < 8; c++) {
                    float4 r = row[c];
                    h0 = fmaf(w2[c * 4 + 0], r.x, h0);
                    h1 = fmaf(w2[c * 4 + 1], r.y, h1);
                    h2 = fmaf(w2[c * 4 + 2], r.z, h2);
                    h3 = fmaf(w2[c * 4 + 3], r.w, h3);
                }
                acc += fmaxf((h0 + h1) + (h2 + h3), 0.f);
            }
        } else {
#pragma unroll 4
            for (int t = 0; t < cnt; t++) {
                int vv = __shfl_sync(0xffffffffu, v, t);
                A[t][j] = fmaxf(pj + g_Q[vv * 32 + j], 0.f);
            }
            __syncwarp();
            for (int t = 0; t < cnt; t++) {
                const float4* row = (const float4*)A[t];
                float h0 = bb2, h1 = 0.f, h2 = 0.f, h3 = 0.f;
#pragma unroll
                for (int c = 0; c < 8; c++) {
                    float4 r = row[c];
                    h0 = fmaf(w2[c * 4 + 0], r.x, h0);
                    h1 = fmaf(w2[c * 4 + 1], r.y, h1);
                    h2 = fmaf(w2[c * 4 + 2], r.z, h2);
                    h3 = fmaf(w2[c * 4 + 3], r.w, h3);
                }
                acc += fmaxf((h0 + h1) + (h2 + h3), 0.f);
            }
        }
    }

    // per-node layer-3: a[u][j] = deg*b3[j] + sum_k W3[j][k] * acc_k
    float r = (float)(eEnd - s) * b3[j];
#pragma unroll
    for (int k = 0; k < 32; k++) {
        float w3k = W3[j * 32 + k];
        r = fmaf(w3k, __shfl_sync(0xffffffffu, acc, k), r);
    }
    g_a[u * 32 + j] = r;
}

// GRU cell on nodes (torch gate order r,z,n). Weights transposed+packed in smem.
__global__ void gru_kernel(const float* __restrict__ Wih,
                           const float* __restrict__ Whh,
                           const float* __restrict__ bih,
                           const float* __restrict__ bhh,
                           float* __restrict__ out, int n_nodes) {
    __shared__ float4 sWi[32][32];
    __shared__ float4 sWh[32][32];
    int tid = threadIdx.x;
    for (int idx = tid; idx < 1024; idx += blockDim.x) {
        int k = idx >> 5, j = idx & 31;
        sWi[k][j] = make_float4(Wih[j * 32 + k], Wih[(j + 32) * 32 + k],
                                Wih[(j + 64) * 32 + k], 0.f);
        sWh[k][j] = make_float4(Whh[j * 32 + k], Whh[(j + 32) * 32 + k],
                                Whh[(j + 64) * 32 + k], 0.f);
    }
    __syncthreads();

    int j = tid & 31;
    int warp = tid >> 5;
    int wpb = blockDim.x >> 5;
    float br = bih[j], bz = bih[j + 32], bn = bih[j + 64];
    float cr = bhh[j], cz = bhh[j + 32], cn = bhh[j + 64];

    for (int u = blockIdx.x * wpb + warp; u < n_nodes; u += gridDim.x * wpb) {
        float x = g_a[u * 32 + j];
        float h = g_node[u * 32 + j];
        float gir = br, giz = bz, gin = bn, ghr = cr, ghz = cz, ghn = cn;
#pragma unroll
        for (int k = 0; k < 32; k++) {
            float xa = __shfl_sync(0xffffffffu, x, k);
            float hb = __shfl_sync(0xffffffffu, h, k);
            float4 wi = sWi[k][j];
            float4 wh = sWh[k][j];
            gir = fmaf(wi.x, xa, gir); giz = fmaf(wi.y, xa, giz); gin = fmaf(wi.z, xa, gin);
            ghr = fmaf(wh.x, hb, ghr); ghz = fmaf(wh.y, hb, ghz); ghn = fmaf(wh.z, hb, ghn);
        }
        float r = 1.f / (1.f + expf(-(gir + ghr)));
        float z = 1.f / (1.f + expf(-(giz + ghz)));
        float nval = tanhf(gin + r * ghn);
        float nh = (1.f - z) * nval + z * h;
        g_node[u * 32 + j] = nh;
        if (out) out[u * 32 + j] = nh;
    }
}

// ---------------- launch ----------------
extern "C" void kernel_launch(void* const* d_in, const int* in_sizes, int n_in,
                              void* d_out, int out_size) {
    const float* pos     = (const float*)d_in[0];
    const float* classes = (const float*)d_in[1];
    const int*   edges   = (const int*)d_in[2];
    int wb = (in_sizes[3] == 1) ? 4 : 3;
    const float* Win = (const float*)d_in[wb + 0];
    const float* bin = (const float*)d_in[wb + 1];
    const float* W1  = (const float*)d_in[wb + 2];
    const float* b1  = (const float*)d_in[wb + 3];
    const float* W2  = (const float*)d_in[wb + 4];
    const float* b2  = (const float*)d_in[wb + 5];
    const float* W3  = (const float*)d_in[wb + 6];
    const float* b3  = (const float*)d_in[wb + 7];
    const float* Wih = (const float*)d_in[wb + 8];
    const float* Whh = (const float*)d_in[wb + 9];
    const float* bih = (const float*)d_in[wb + 10];
    const float* bhh = (const float*)d_in[wb + 11];

    int n_nodes = in_sizes[0] / 3;
    int n_edges = in_sizes[2] / 2;
    int n2e = 2 * n_edges;
    float* out = (float*)d_out;

    // once-per-launch prep
    zero_cnt_kernel<<<(n_nodes + 255) / 256, 256>>>(n_nodes);
    embed_pvc_kernel<<<(n_nodes + 7) / 8, 256>>>(classes, pos, Win, bin, W1, n_nodes);
    count_kernel<<<(n2e + 255) / 256, 256>>>(edges, n2e);
    scan_kernel<<<1, 1024>>>(n_nodes);
    init_cur_kernel<<<(n_nodes + 255) / 256, 256>>>(n_nodes);
    scatter_kernel<<<(n2e + 255) / 256, 256>>>(edges, n_edges);

    for (int it = 0; it < 6; ++it) {
        pq_kernel<<<(n_nodes + 7) / 8, 256>>>(W1, b1, n_nodes);
        edge_kernel<<<(n_nodes + 7) / 8, 256>>>(W2, b2, W3, b3, n_nodes);
        gru_kernel<<<512, 256>>>(Wih, Whh, bih, bhh,
                                 (it == 5) ? out : (float*)nullptr, n_nodes);
    }
}

// round 3
// speedup vs baseline: 3.6156x; 2.6712x over previous
#include <cuda_runtime.h>

#define NN 50000
#define NE 800000
#define NB 64

// ---------------- scratch (device globals: allocation-free) ----------------
__device__ __align__(16) float g_node[NN * 32];
__device__ __align__(16) float g_P[NN * 32];
__device__ __align__(16) float g_Q[NN * 32];
__device__ __align__(16) float g_pvc[NN * 32];
__device__ int   g_cnt[NN];
__device__ int   g_off[NN + 1];
__device__ int   g_cur[NN];
__device__ int   g_csr[2 * NE];
__device__ int   g_bsum[NB];
__device__ int   g_bpre[NB];

// ---------------- prep kernels ----------------
__global__ void zero_cnt_kernel(int n) {
    int i = blockIdx.x * blockDim.x + threadIdx.x;
    if (i < n) g_cnt[i] = 0;
}

__global__ void embed_pvc_kernel(const float* __restrict__ classes,
                                 const float* __restrict__ pos,
                                 const float* __restrict__ Win,
                                 const float* __restrict__ bin,
                                 const float* __restrict__ W1,
                                 int n_nodes) {
    int warp = (blockIdx.x * blockDim.x + threadIdx.x) >> 5;
    int j = threadIdx.x & 31;
    if (warp >= n_nodes) return;
    int u = warp;

    float w[16];
#pragma unroll
    for (int k = 0; k < 16; k++) w[k] = Win[j * 16 + k];
    float c = (j < 16) ? classes[u * 16 + j] : 0.f;
    float acc = bin[j];
#pragma unroll
    for (int k = 0; k < 16; k++)
        acc = fmaf(w[k], __shfl_sync(0xffffffffu, c, k), acc);
    g_node[u * 32 + j] = acc;

    float p0 = pos[u * 3 + 0], p1 = pos[u * 3 + 1], p2 = pos[u * 3 + 2];
    float pv = p0 * W1[j * 67 + 64] + p1 * W1[j * 67 + 65] + p2 * W1[j * 67 + 66];
    g_pvc[u * 32 + j] = pv;
}

__global__ void count_kernel(const int* __restrict__ e, int n2e) {
    int i = blockIdx.x * blockDim.x + threadIdx.x;
    if (i < n2e) atomicAdd(&g_cnt[e[i]], 1);
}

// hierarchical scan: block sums -> scan of sums -> per-block scan+write
__global__ void scan1_kernel(int n, int seg) {
    int b = blockIdx.x;
    int beg = b * seg, end = min(beg + seg, n);
    int tid = threadIdx.x;
    int s = 0;
    for (int i = beg + tid; i < end; i += 256) s += g_cnt[i];
    __shared__ int sm[8];
    int lane = tid & 31, w = tid >> 5;
#pragma unroll
    for (int o = 16; o >= 1; o >>= 1) s += __shfl_down_sync(0xffffffffu, s, o);
    if (lane == 0) sm[w] = s;
    __syncthreads();
    if (tid == 0) {
        int t = 0;
#pragma unroll
        for (int k = 0; k < 8; k++) t += sm[k];
        g_bsum[b] = t;
    }
}

__global__ void scan2_kernel() {  // 1 block, 64 threads
    int tid = threadIdx.x;
    int s = g_bsum[tid];
    int lane = tid & 31, w = tid >> 5;
    int v = s;
#pragma unroll
    for (int o = 1; o < 32; o <<= 1) {
        int t = __shfl_up_sync(0xffffffffu, v, o);
        if (lane >= o) v += t;
    }
    __shared__ int w0tot;
    if (tid == 31) w0tot = v;
    __syncthreads();
    int incl = v + (w == 1 ? w0tot : 0);
    g_bpre[tid] = incl - s;
}

__global__ void scan3_kernel(int n, int seg) {
    int b = blockIdx.x, tid = threadIdx.x;
    int beg = b * seg, end = min(beg + seg, n);
    int len = max(end - beg, 0);
    int c = (len + 255) / 256;
    int tb = min(beg + tid * c, end), te = min(tb + c, end);
    int s = 0;
    for (int i = tb; i < te; i++) s += g_cnt[i];
    int lane = tid & 31, w = tid >> 5;
    int v = s;
#pragma unroll
    for (int o = 1; o < 32; o <<= 1) {
        int t = __shfl_up_sync(0xffffffffu, v, o);
        if (lane >= o) v += t;
    }
    __shared__ int wt[8], wpre[8];
    if (lane == 31) wt[w] = v;
    __syncthreads();
    if (tid < 8) {
        int x = wt[tid];
#pragma unroll
        for (int o = 1; o < 8; o <<= 1) {
            int t = __shfl_up_sync(0xffu, x, o);
            if (tid >= o) x += t;
        }
        wpre[tid] = x;
    }
    __syncthreads();
    int excl = (v - s) + (w > 0 ? wpre[w - 1] : 0);
    int run = g_bpre[b] + excl;
    for (int i = tb; i < te; i++) {
        g_off[i] = run;
        g_cur[i] = run;
        run += g_cnt[i];
    }
    if (b == gridDim.x - 1 && tid == 255) g_off[n] = run;
}

__global__ void scatter_kernel(const int* __restrict__ e, int nE) {
    int i = blockIdx.x * blockDim.x + threadIdx.x;
    if (i >= 2 * nE) return;
    int src = e[i];
    int dst = (i < nE) ? e[i + nE] : e[i - nE];
    int slot = atomicAdd(&g_cur[src], 1);
    g_csr[slot] = dst;
}

// ---------------- per-iteration kernels ----------------
// persistent: P = node@W1a.T + b1 - pvc ; Q = node@W1b.T + pvc
__global__ void __launch_bounds__(256) pq_kernel(const float* __restrict__ W1,
                                                 const float* __restrict__ b1,
                                                 int n_nodes) {
    int j = threadIdx.x & 31;
    int wl = threadIdx.x >> 5;
    float wa[32], wb[32];
#pragma unroll
    for (int k = 0; k < 32; k++) {
        wa[k] = W1[j * 67 + k];
        wb[k] = W1[j * 67 + 32 + k];
    }
    float bj = b1[j];
    int nw = gridDim.x * 8;
    for (int u = blockIdx.x * 8 + wl; u < n_nodes; u += nw) {
        float nd = g_node[u * 32 + j];
        float p = 0.f, q = 0.f;
#pragma unroll
        for (int k = 0; k < 32; k++) {
            float v = __shfl_sync(0xffffffffu, nd, k);
            p = fmaf(wa[k], v, p);
            q = fmaf(wb[k], v, q);
        }
        float pv = g_pvc[u * 32 + j];
        g_P[u * 32 + j] = p + bj - pv;
        g_Q[u * 32 + j] = q + pv;
    }
}

// Fused hot kernel: persistent warp per node-stream.
//   pass1 (vectorized): 8-lane groups gather Q rows via LDG.128, relu, STS.128
//   pass2: LDS.128 broadcast rows x register W2, accumulate relu(h2)
//   epilogue: a = acc@W3.T + deg*b3 (W3 from smem), then GRU -> g_node (+out)
__global__ void __launch_bounds__(128) edge_gru_kernel(
        const float* __restrict__ W2, const float* __restrict__ b2,
        const float* __restrict__ W3, const float* __restrict__ b3,
        const float* __restrict__ Wih, const float* __restrict__ Whh,
        const float* __restrict__ bih, const float* __restrict__ bhh,
        float* __restrict__ out, int n_nodes) {
    __shared__ float A_s[4][32][32];     // 16KB per-warp h1 tile
    __shared__ float2 sWi2[32][32];      // 8KB (r,z) of Wih^T
    __shared__ float  sWin[32][32];      // 4KB n of Wih^T
    __shared__ float2 sWh2[32][32];      // 8KB
    __shared__ float  sWhn[32][32];      // 4KB
    __shared__ float  sW3[32][32];       // 4KB W3^T
    int tid = threadIdx.x, wl = tid >> 5, j = tid & 31;

    for (int idx = tid; idx < 1024; idx += 128) {
        int k = idx >> 5, jj = idx & 31;
        sWi2[k][jj] = make_float2(Wih[jj * 32 + k], Wih[(jj + 32) * 32 + k]);
        sWin[k][jj] = Wih[(jj + 64) * 32 + k];
        sWh2[k][jj] = make_float2(Whh[jj * 32 + k], Whh[(jj + 32) * 32 + k]);
        sWhn[k][jj] = Whh[(jj + 64) * 32 + k];
        sW3[k][jj]  = W3[jj * 32 + k];
    }
    __syncthreads();

    float w2[32];
#pragma unroll
    for (int k = 0; k < 32; k++) w2[k] = W2[j * 32 + k];
    float bb2 = b2[j], bb3 = b3[j];
    float br = bih[j], bz = bih[j + 32], bn = bih[j + 64];
    float cr = bhh[j], cz = bhh[j + 32], cn = bhh[j + 64];

    float (*A)[32] = A_s[wl];
    int sub = j >> 3;     // row subgroup 0..3
    int qcol = j & 7;     // float4 column
    int nw = gridDim.x * 4;

    for (int u = blockIdx.x * 4 + wl; u < n_nodes; u += nw) {
        float pj = g_P[(size_t)u * 32 + j];
        float4 pq4;
        pq4.x = __shfl_sync(0xffffffffu, pj, qcol * 4 + 0);
        pq4.y = __shfl_sync(0xffffffffu, pj, qcol * 4 + 1);
        pq4.z = __shfl_sync(0xffffffffu, pj, qcol * 4 + 2);
        pq4.w = __shfl_sync(0xffffffffu, pj, qcol * 4 + 3);

        int s = g_off[u], e = g_off[u + 1];
        float acc = 0.f;

        for (int base = s; base < e; base += 32) {
            int cnt = min(32, e - base);
            int v = (base + j < e) ? g_csr[base + j] : 0;
            __syncwarp();
            if (cnt == 32) {
#pragma unroll
                for (int it = 0; it < 8; it++) {
                    int row = it * 4 + sub;
                    int vv = __shfl_sync(0xffffffffu, v, row);
                    float4 q = *(const float4*)&g_Q[(size_t)vv * 32 + qcol * 4];
                    float4 hh;
                    hh.x = fmaxf(pq4.x + q.x, 0.f);
                    hh.y = fmaxf(pq4.y + q.y, 0.f);
                    hh.z = fmaxf(pq4.z + q.z, 0.f);
                    hh.w = fmaxf(pq4.w + q.w, 0.f);
                    *(float4*)&A[row][qcol * 4] = hh;
                }
                __syncwarp();
#pragma unroll 4
                for (int t = 0; t < 32; t++) {
                    const float4* row = (const float4*)A[t];
                    float h0 = bb2, h1 = 0.f, h2 = 0.f, h3 = 0.f;
#pragma unroll
                    for (int c = 0; c < 8; c++) {
                        float4 r = row[c];
                        h0 = fmaf(w2[c * 4 + 0], r.x, h0);
                        h1 = fmaf(w2[c * 4 + 1], r.y, h1);
                        h2 = fmaf(w2[c * 4 + 2], r.z, h2);
                        h3 = fmaf(w2[c * 4 + 3], r.w, h3);
                    }
                    acc += fmaxf((h0 + h1) + (h2 + h3), 0.f);
                }
            } else {
                for (int t = 0; t < cnt; t++) {
                    int vv = __shfl_sync(0xffffffffu, v, t);
                    A[t][j] = fmaxf(pj + g_Q[(size_t)vv * 32 + j], 0.f);
                }
                __syncwarp();
                for (int t = 0; t < cnt; t++) {
                    const float4* row = (const float4*)A[t];
                    float h0 = bb2, h1 = 0.f, h2 = 0.f, h3 = 0.f;
#pragma unroll
                    for (int c = 0; c < 8; c++) {
                        float4 r = row[c];
                        h0 = fmaf(w2[c * 4 + 0], r.x, h0);
                        h1 = fmaf(w2[c * 4 + 1], r.y, h1);
                        h2 = fmaf(w2[c * 4 + 2], r.z, h2);
                        h3 = fmaf(w2[c * 4 + 3], r.w, h3);
                    }
                    acc += fmaxf((h0 + h1) + (h2 + h3), 0.f);
                }
            }
        }

        // layer-3 epilogue (commutes with segment-sum)
        float a = (float)(e - s) * bb3;
#pragma unroll
        for (int k = 0; k < 32; k++)
            a = fmaf(sW3[k][j], __shfl_sync(0xffffffffu, acc, k), a);

        // GRU (torch gate order r,z,n)
        float h = g_node[(size_t)u * 32 + j];
        float gir = br, giz = bz, gin = bn, ghr = cr, ghz = cz, ghn = cn;
#pragma unroll
        for (int k = 0; k < 32; k++) {
            float xa = __shfl_sync(0xffffffffu, a, k);
            float hb = __shfl_sync(0xffffffffu, h, k);
            float2 wi = sWi2[k][j];
            float win = sWin[k][j];
            float2 wh = sWh2[k][j];
            float whn = sWhn[k][j];
            gir = fmaf(wi.x, xa, gir); giz = fmaf(wi.y, xa, giz); gin = fmaf(win, xa, gin);
            ghr = fmaf(wh.x, hb, ghr); ghz = fmaf(wh.y, hb, ghz); ghn = fmaf(whn, hb, ghn);
        }
        float r = 1.f / (1.f + expf(-(gir + ghr)));
        float z = 1.f / (1.f + expf(-(giz + ghz)));
        float nv = tanhf(gin + r * ghn);
        float nh = (1.f - z) * nv + z * h;
        g_node[(size_t)u * 32 + j] = nh;
        if (out) out[(size_t)u * 32 + j] = nh;
    }
}

// ---------------- launch ----------------
extern "C" void kernel_launch(void* const* d_in, const int* in_sizes, int n_in,
                              void* d_out, int out_size) {
    const float* pos     = (const float*)d_in[0];
    const float* classes = (const float*)d_in[1];
    const int*   edges   = (const int*)d_in[2];
    int wb = (in_sizes[3] == 1) ? 4 : 3;
    const float* Win = (const float*)d_in[wb + 0];
    const float* bin = (const float*)d_in[wb + 1];
    const float* W1  = (const float*)d_in[wb + 2];
    const float* b1  = (const float*)d_in[wb + 3];
    const float* W2  = (const float*)d_in[wb + 4];
    const float* b2  = (const float*)d_in[wb + 5];
    const float* W3  = (const float*)d_in[wb + 6];
    const float* b3  = (const float*)d_in[wb + 7];
    const float* Wih = (const float*)d_in[wb + 8];
    const float* Whh = (const float*)d_in[wb + 9];
    const float* bih = (const float*)d_in[wb + 10];
    const float* bhh = (const float*)d_in[wb + 11];

    int n_nodes = in_sizes[0] / 3;
    int n_edges = in_sizes[2] / 2;
    int n2e = 2 * n_edges;
    float* out = (float*)d_out;
    int seg = (n_nodes + NB - 1) / NB;

    zero_cnt_kernel<<<(n_nodes + 255) / 256, 256>>>(n_nodes);
    embed_pvc_kernel<<<(n_nodes + 7) / 8, 256>>>(classes, pos, Win, bin, W1, n_nodes);
    count_kernel<<<(n2e + 255) / 256, 256>>>(edges, n2e);
    scan1_kernel<<<NB, 256>>>(n_nodes, seg);
    scan2_kernel<<<1, 64>>>();
    scan3_kernel<<<NB, 256>>>(n_nodes, seg);
    scatter_kernel<<<(n2e + 255) / 256, 256>>>(edges, n_edges);

    for (int it = 0; it < 6; ++it) {
        pq_kernel<<<296, 256>>>(W1, b1, n_nodes);
        edge_gru_kernel<<<740, 128>>>(W2, b2, W3, b3, Wih, Whh, bih, bhh,
                                      (it == 5) ? out : (float*)nullptr, n_nodes);
    }
}